// round 1
// baseline (speedup 1.0000x reference)
#include <cuda_runtime.h>
#include <cstdint>
#include <cstddef>

#define N_NODES 50000
#define N_EDGES 1000000
#define DIM     128
#define HID     64

// Scratch for per-node projections (25.6 MB total) — __device__ globals per harness rules.
__device__ __align__(16) float g_PA[50048 * HID];
__device__ __align__(16) float g_PB[50048 * HID];

// ---------------- packed f32x2 helpers (Blackwell sm_100+) ----------------
__device__ __forceinline__ unsigned long long pk2(float lo, float hi) {
    unsigned long long r;
    asm("mov.b64 %0, {%1, %2};" : "=l"(r) : "f"(lo), "f"(hi));
    return r;
}
__device__ __forceinline__ float2 upk2(unsigned long long v) {
    float2 r;
    asm("mov.b64 {%0, %1}, %2;" : "=f"(r.x), "=f"(r.y) : "l"(v));
    return r;
}
__device__ __forceinline__ void fma2(unsigned long long& d,
                                     unsigned long long a,
                                     unsigned long long b) {
    asm("fma.rn.f32x2 %0, %1, %2, %3;" : "=l"(d) : "l"(a), "l"(b), "l"(d));
}

// ============================================================================
// Prep: PA[n][j] = sum_k x[n][k]*W1[j][k],  PB[n][j] = sum_k x[n][k]*W1[j][128+k]
// Block: 256 threads = 8 warps (each warp owns 8 consecutive j), 64 nodes/block.
// Lane = node within half-tile; each thread handles 2 nodes x 8 j x {A,B}.
// smem: sW = W1[:, 0:256] (64KB, warp-uniform reads), sxT = x tile transposed
// to [k4][node][4] (32KB, lane-consecutive 16B -> conflict-free LDS.128).
// ============================================================================
__global__ void __launch_bounds__(256, 2) prep_kernel(
    const float* __restrict__ x, const float* __restrict__ W1)
{
    extern __shared__ float smem[];
    float* sW  = smem;            // 16384 floats: [j][256]
    float* sxT = smem + 16384;    // 8192 floats:  [k4][64][4]

    const int tid   = threadIdx.x;
    const int nbase = blockIdx.x * 64;

    for (int idx = tid; idx < 16384; idx += 256) {
        int j = idx >> 8, c = idx & 255;
        sW[idx] = W1[j * 384 + c];
    }
    for (int idx = tid; idx < 8192; idx += 256) {
        int nl = idx >> 7, k = idx & 127;
        int node = nbase + nl;
        float v = (node < N_NODES) ? x[node * DIM + k] : 0.f;
        sxT[(k >> 2) * 256 + (nl << 2) + (k & 3)] = v;
    }
    __syncthreads();

    const int lane  = tid & 31;
    const int w     = tid >> 5;
    const int jbase = w * 8;

    unsigned long long aA[2][8], aB[2][8];
    #pragma unroll
    for (int n = 0; n < 2; n++)
        #pragma unroll
        for (int jj = 0; jj < 8; jj++) { aA[n][jj] = 0ull; aB[n][jj] = 0ull; }

    const ulonglong2* xT2 = (const ulonglong2*)sxT;

    #pragma unroll 1
    for (int k4 = 0; k4 < 32; k4++) {
        ulonglong2 xv0 = xT2[(k4 << 6) + lane];
        ulonglong2 xv1 = xT2[(k4 << 6) + 32 + lane];
        #pragma unroll
        for (int jj = 0; jj < 8; jj++) {
            const ulonglong2* wr = (const ulonglong2*)(sW + ((jbase + jj) << 8));
            ulonglong2 wa = wr[k4];        // W1[j][4k4 .. 4k4+3]
            ulonglong2 wb = wr[32 + k4];   // W1[j][128+4k4 .. ]
            fma2(aA[0][jj], xv0.x, wa.x);  fma2(aA[0][jj], xv0.y, wa.y);
            fma2(aA[1][jj], xv1.x, wa.x);  fma2(aA[1][jj], xv1.y, wa.y);
            fma2(aB[0][jj], xv0.x, wb.x);  fma2(aB[0][jj], xv0.y, wb.y);
            fma2(aB[1][jj], xv1.x, wb.x);  fma2(aB[1][jj], xv1.y, wb.y);
        }
    }

    #pragma unroll
    for (int n = 0; n < 2; n++) {
        int node = nbase + n * 32 + lane;
        if (node < N_NODES) {
            #pragma unroll
            for (int jj = 0; jj < 8; jj++) {
                float2 a = upk2(aA[n][jj]);
                float2 b = upk2(aB[n][jj]);
                g_PA[node * HID + jbase + jj] = a.x + a.y;
                g_PB[node * HID + jbase + jj] = b.x + b.y;
            }
        }
    }
}

// ============================================================================
// Main: one thread per edge.
//   h1 = relu(PA[src] + PB[dst] + b1 + e @ W1c^T)
//   h2 = relu(h1 @ W2^T + b2); score = h2 . W3 + b3
// sW1c staged as [kc][j][4] -> warp-uniform broadcast LDS.128 in hot loop.
// 64 packed f32x2 accumulators; e row streamed with 1-iter prefetch.
// ============================================================================
__global__ void __launch_bounds__(128, 3) edge_kernel(
    const int*   __restrict__ ei,
    const float* __restrict__ e,
    const float* __restrict__ W1,
    const float* __restrict__ b1,
    const float* __restrict__ W2,
    const float* __restrict__ b2,
    const float* __restrict__ W3,
    const float* __restrict__ b3,
    float*       __restrict__ out)
{
    __shared__ float sW1c[8192];  // 32 KB: [kc][j][4] = W1[j][256 + 4kc + c]
    __shared__ float sW2[4096];   // 16 KB: [j][64]

    const int tid = threadIdx.x;
    for (int idx = tid; idx < 8192; idx += 128) {
        int j = idx >> 7, k = idx & 127;
        sW1c[(k >> 2) * 256 + (j << 2) + (k & 3)] = W1[j * 384 + 256 + k];
    }
    for (int idx = tid; idx < 4096; idx += 128) sW2[idx] = W2[idx];
    __syncthreads();

    const int eidx = blockIdx.x * 128 + tid;
    if (eidx >= N_EDGES) return;

    const int src = ei[eidx];
    const int dst = ei[N_EDGES + eidx];

    unsigned long long hacc[64];
    {
        const float4* pa = (const float4*)(g_PA + src * HID);
        const float4* pb = (const float4*)(g_PB + dst * HID);
        const float4* bv = (const float4*)b1;
        #pragma unroll
        for (int q = 0; q < 16; q++) {
            float4 a = pa[q];
            float4 b = pb[q];
            float4 c = __ldg(&bv[q]);
            hacc[4*q + 0] = pk2(a.x + b.x + c.x, 0.f);
            hacc[4*q + 1] = pk2(a.y + b.y + c.y, 0.f);
            hacc[4*q + 2] = pk2(a.z + b.z + c.z, 0.f);
            hacc[4*q + 3] = pk2(a.w + b.w + c.w, 0.f);
        }
    }

    // Layer 1: accumulate e @ W1c^T over 32 chunks of 4 k-values.
    const ulonglong2* ee = (const ulonglong2*)(e + (size_t)eidx * DIM);
    ulonglong2 ev = ee[0];
    #pragma unroll 1
    for (int kc = 0; kc < 32; kc++) {
        ulonglong2 evn;
        if (kc < 31) evn = ee[kc + 1];        // prefetch next e chunk
        const ulonglong2* wr = (const ulonglong2*)(sW1c + (kc << 8));
        #pragma unroll
        for (int j = 0; j < 64; j++) {
            ulonglong2 wv = wr[j];            // broadcast LDS.128
            fma2(hacc[j], ev.x, wv.x);
            fma2(hacc[j], ev.y, wv.y);
        }
        ev = evn;
    }

    // Horizontal reduce + relu, repack pairs for layer 2.
    unsigned long long f1[32];
    #pragma unroll
    for (int p = 0; p < 32; p++) {
        float2 a = upk2(hacc[2*p]);
        float2 b = upk2(hacc[2*p + 1]);
        f1[p] = pk2(fmaxf(a.x + a.y, 0.f), fmaxf(b.x + b.y, 0.f));
    }

    // Layers 2 + 3 fused. Two accumulator chains per output to keep dep
    // latency (16*4 cyc) under the issue budget at 3 warps/SMSP.
    float score = __ldg(b3);
    #pragma unroll 1
    for (int j2 = 0; j2 < 64; j2++) {
        const ulonglong2* wr = (const ulonglong2*)(sW2 + (j2 << 6));
        unsigned long long acc0 = 0ull, acc1 = 0ull;
        #pragma unroll
        for (int q = 0; q < 16; q++) {
            ulonglong2 wv = wr[q];            // broadcast LDS.128
            fma2(acc0, f1[2*q],     wv.x);
            fma2(acc1, f1[2*q + 1], wv.y);
        }
        float2 a0 = upk2(acc0), a1 = upk2(acc1);
        float h2 = fmaxf(a0.x + a0.y + a1.x + a1.y + __ldg(&b2[j2]), 0.f);
        score = fmaf(h2, __ldg(&W3[j2]), score);
    }

    out[eidx] = score;
}

// ============================================================================
extern "C" void kernel_launch(void* const* d_in, const int* in_sizes, int n_in,
                              void* d_out, int out_size)
{
    const int*   ei = (const int*)  d_in[0];
    const float* x  = (const float*)d_in[1];
    const float* e  = (const float*)d_in[2];
    const float* W1 = (const float*)d_in[3];
    const float* b1 = (const float*)d_in[4];
    const float* W2 = (const float*)d_in[5];
    const float* b2 = (const float*)d_in[6];
    const float* W3 = (const float*)d_in[7];
    const float* b3 = (const float*)d_in[8];
    float* out = (float*)d_out;

    (void)in_sizes; (void)n_in; (void)out_size;

    cudaFuncSetAttribute(prep_kernel,
                         cudaFuncAttributeMaxDynamicSharedMemorySize, 98304);

    // 782 blocks x 64 nodes covers 50000 nodes.
    prep_kernel<<<782, 256, 98304>>>(x, W1);

    // 7813 blocks x 128 threads covers 1,000,000 edges.
    edge_kernel<<<7813, 128>>>(ei, e, W1, b1, W2, b2, W3, b3, out);
}

// round 2
// speedup vs baseline: 1.0032x; 1.0032x over previous
#include <cuda_runtime.h>
#include <cstdint>
#include <cstddef>

#define N_NODES 50000
#define N_EDGES 1000000
#define DIM     128
#define HID     64
#define TE      128     // edges per block
#define TH      256     // threads per block

typedef unsigned long long u64;

// Per-node projection scratch (25.6 MB) — __device__ globals per harness rules.
__device__ __align__(16) float g_PA[50048 * HID];
__device__ __align__(16) float g_PB[50048 * HID];

// ---------------- packed f32x2 helpers ----------------
__device__ __forceinline__ u64 pk2(float lo, float hi) {
    u64 r; asm("mov.b64 %0, {%1, %2};" : "=l"(r) : "f"(lo), "f"(hi)); return r;
}
__device__ __forceinline__ u64 splat2(float f) {
    u64 r; asm("mov.b64 %0, {%1, %1};" : "=l"(r) : "f"(f)); return r;
}
__device__ __forceinline__ float2 upk2(u64 v) {
    float2 r; asm("mov.b64 {%0, %1}, %2;" : "=f"(r.x), "=f"(r.y) : "l"(v)); return r;
}
__device__ __forceinline__ void fma2(u64& d, u64 a, u64 b) {
    asm("fma.rn.f32x2 %0, %1, %2, %3;" : "=l"(d) : "l"(a), "l"(b), "l"(d));
}

// ============================================================================
// Prep: PA[n][j] = x[n] . W1[j][0:128],  PB[n][j] = x[n] . W1[j][128:256]
// (unchanged from R1 — not the bottleneck)
// ============================================================================
__global__ void __launch_bounds__(256, 2) prep_kernel(
    const float* __restrict__ x, const float* __restrict__ W1)
{
    extern __shared__ float smem[];
    float* sW  = smem;            // 16384 floats: [j][256]
    float* sxT = smem + 16384;    // 8192 floats:  [k4][64][4]

    const int tid   = threadIdx.x;
    const int nbase = blockIdx.x * 64;

    for (int idx = tid; idx < 16384; idx += 256) {
        int j = idx >> 8, c = idx & 255;
        sW[idx] = W1[j * 384 + c];
    }
    for (int idx = tid; idx < 8192; idx += 256) {
        int nl = idx >> 7, k = idx & 127;
        int node = nbase + nl;
        float v = (node < N_NODES) ? x[node * DIM + k] : 0.f;
        sxT[(k >> 2) * 256 + (nl << 2) + (k & 3)] = v;
    }
    __syncthreads();

    const int lane  = tid & 31;
    const int w     = tid >> 5;
    const int jbase = w * 8;

    u64 aA[2][8], aB[2][8];
    #pragma unroll
    for (int n = 0; n < 2; n++)
        #pragma unroll
        for (int jj = 0; jj < 8; jj++) { aA[n][jj] = 0ull; aB[n][jj] = 0ull; }

    const ulonglong2* xT2 = (const ulonglong2*)sxT;

    #pragma unroll 1
    for (int k4 = 0; k4 < 32; k4++) {
        ulonglong2 xv0 = xT2[(k4 << 6) + lane];
        ulonglong2 xv1 = xT2[(k4 << 6) + 32 + lane];
        #pragma unroll
        for (int jj = 0; jj < 8; jj++) {
            const ulonglong2* wr = (const ulonglong2*)(sW + ((jbase + jj) << 8));
            ulonglong2 wa = wr[k4];
            ulonglong2 wb = wr[32 + k4];
            fma2(aA[0][jj], xv0.x, wa.x);  fma2(aA[0][jj], xv0.y, wa.y);
            fma2(aA[1][jj], xv1.x, wa.x);  fma2(aA[1][jj], xv1.y, wa.y);
            fma2(aB[0][jj], xv0.x, wb.x);  fma2(aB[0][jj], xv0.y, wb.y);
            fma2(aB[1][jj], xv1.x, wb.x);  fma2(aB[1][jj], xv1.y, wb.y);
        }
    }

    #pragma unroll
    for (int n = 0; n < 2; n++) {
        int node = nbase + n * 32 + lane;
        if (node < N_NODES) {
            #pragma unroll
            for (int jj = 0; jj < 8; jj++) {
                float2 a = upk2(aA[n][jj]);
                float2 b = upk2(aB[n][jj]);
                g_PA[node * HID + jbase + jj] = a.x + a.y;
                g_PB[node * HID + jbase + jj] = b.x + b.y;
            }
        }
    }
}

// ============================================================================
// Edge kernel — register-tiled GEMM.
// Block: 256 threads, tile = 128 edges x 64 outputs.
// Thread (equad = tid>>3, joct = tid&7) computes 4 edges x 8 j.
// Per k-step: 1 LDS.128 (a, 4-lane broadcast) + 2 LDS.128 (b, broadcast)
//             + 4 splats + 16 fma2  (32 FMA).
// Activation smem uses swizzle col = (edge + 4*(k>>2)) & 127:
//   conflict-free STS.32 on transpose-store, broadcast LDS.128 on read.
// ============================================================================
__global__ void __launch_bounds__(TH, 2) edge_kernel(
    const int*   __restrict__ ei,
    const float* __restrict__ e,
    const float* __restrict__ W1,
    const float* __restrict__ b1,
    const float* __restrict__ W2,
    const float* __restrict__ b2,
    const float* __restrict__ W3,
    const float* __restrict__ b3,
    float*       __restrict__ out)
{
    extern __shared__ float sm[];
    float* sW1 = sm;             // 8192: [k:128][j:64]  = W1[j][256+k]
    float* sW2 = sm + 8192;      // 4096: [k:64][j:64]   = W2[j][k]
    float* sB1 = sm + 12288;     // 64
    float* sB2 = sm + 12352;     // 64
    float* sW3 = sm + 12416;     // 64
    float* eT  = sm + 12480;     // 8192: chunk [k:64][col:128]; aliased as h1T

    const int tid   = threadIdx.x;
    const int e0    = blockIdx.x * TE;
    const int equad = tid >> 3;
    const int joct  = tid & 7;
    const int j0    = joct * 8;
    const int ebase = e0 + equad * 4;
    const int ecol  = equad * 4;

    // ---- stage weights (transposed) ----
    for (int i = tid; i < 8192; i += TH) {
        int j = i & 63, k = i >> 6;
        sW1[k * 64 + j] = W1[j * 384 + 256 + k];
    }
    for (int i = tid; i < 4096; i += TH) {
        int j = i & 63, k = i >> 6;
        sW2[k * 64 + j] = W2[j * 64 + k];
    }
    if (tid < 64) { sB1[tid] = b1[tid]; sB2[tid] = b2[tid]; sW3[tid] = W3[tid]; }

    // ---- stage e chunk 0 (k = 0..63), transposed + swizzled ----
    #pragma unroll
    for (int i = tid; i < 2048; i += TH) {
        int edge = i & 127, k4 = i >> 7;                 // k4: 0..15
        int ge = e0 + edge;
        float4 v = make_float4(0.f, 0.f, 0.f, 0.f);
        if (ge < N_EDGES) v = *(const float4*)(e + (size_t)ge * DIM + k4 * 4);
        int w = (edge + 4 * k4) & 127;
        int kk = k4 * 4;
        eT[(kk + 0) * 128 + w] = v.x;
        eT[(kk + 1) * 128 + w] = v.y;
        eT[(kk + 2) * 128 + w] = v.z;
        eT[(kk + 3) * 128 + w] = v.w;
    }

    // ---- edge indices (before sync; independent of smem) ----
    int srcs[4], dsts[4];
    {
        bool okq = (ebase + 3 < N_EDGES);
        if (okq) {
            int4 s4 = *(const int4*)(ei + ebase);
            int4 d4 = *(const int4*)(ei + N_EDGES + ebase);
            srcs[0]=s4.x; srcs[1]=s4.y; srcs[2]=s4.z; srcs[3]=s4.w;
            dsts[0]=d4.x; dsts[1]=d4.y; dsts[2]=d4.z; dsts[3]=d4.w;
        } else {
            #pragma unroll
            for (int q = 0; q < 4; q++) {
                int ge = ebase + q;
                srcs[q] = (ge < N_EDGES) ? ei[ge] : 0;
                dsts[q] = (ge < N_EDGES) ? ei[N_EDGES + ge] : 0;
            }
        }
    }

    __syncthreads();

    // ---- init accumulators: PA[src] + PB[dst] + b1 (j slice j0..j0+7) ----
    u64 acc[4][4];
    {
        float4 bb0 = *(const float4*)&sB1[j0];
        float4 bb1 = *(const float4*)&sB1[j0 + 4];
        #pragma unroll
        for (int q = 0; q < 4; q++) {
            float4 pa0 = *(const float4*)(g_PA + (size_t)srcs[q] * HID + j0);
            float4 pa1 = *(const float4*)(g_PA + (size_t)srcs[q] * HID + j0 + 4);
            float4 pb0 = *(const float4*)(g_PB + (size_t)dsts[q] * HID + j0);
            float4 pb1 = *(const float4*)(g_PB + (size_t)dsts[q] * HID + j0 + 4);
            acc[q][0] = pk2(pa0.x + pb0.x + bb0.x, pa0.y + pb0.y + bb0.y);
            acc[q][1] = pk2(pa0.z + pb0.z + bb0.z, pa0.w + pb0.w + bb0.w);
            acc[q][2] = pk2(pa1.x + pb1.x + bb1.x, pa1.y + pb1.y + bb1.y);
            acc[q][3] = pk2(pa1.z + pb1.z + bb1.z, pa1.w + pb1.w + bb1.w);
        }
    }

    // ---- layer 1 GEMM: two K-chunks of 64 ----
    #pragma unroll 1
    for (int ck = 0; ck < 2; ck++) {
        const int kofs = ck * 64;

        #pragma unroll 4
        for (int k = 0; k < 64; k++) {
            float4 av = *(const float4*)&eT[k * 128 + ((ecol + ((k >> 2) << 2)) & 127)];
            ulonglong2 blo = *(const ulonglong2*)&sW1[(kofs + k) * 64 + j0];
            ulonglong2 bhi = *(const ulonglong2*)&sW1[(kofs + k) * 64 + j0 + 4];
            u64 s0 = splat2(av.x), s1 = splat2(av.y), s2 = splat2(av.z), s3 = splat2(av.w);
            fma2(acc[0][0], s0, blo.x); fma2(acc[0][1], s0, blo.y);
            fma2(acc[0][2], s0, bhi.x); fma2(acc[0][3], s0, bhi.y);
            fma2(acc[1][0], s1, blo.x); fma2(acc[1][1], s1, blo.y);
            fma2(acc[1][2], s1, bhi.x); fma2(acc[1][3], s1, bhi.y);
            fma2(acc[2][0], s2, blo.x); fma2(acc[2][1], s2, blo.y);
            fma2(acc[2][2], s2, bhi.x); fma2(acc[2][3], s2, bhi.y);
            fma2(acc[3][0], s3, blo.x); fma2(acc[3][1], s3, blo.y);
            fma2(acc[3][2], s3, bhi.x); fma2(acc[3][3], s3, bhi.y);
        }

        if (ck == 0) {
            // stage e chunk 1 into the same buffer
            __syncthreads();
            #pragma unroll
            for (int i = tid; i < 2048; i += TH) {
                int edge = i & 127, k4 = i >> 7;
                int ge = e0 + edge;
                float4 v = make_float4(0.f, 0.f, 0.f, 0.f);
                if (ge < N_EDGES) v = *(const float4*)(e + (size_t)ge * DIM + 64 + k4 * 4);
                int w = (edge + 4 * k4) & 127;
                int kk = k4 * 4;
                eT[(kk + 0) * 128 + w] = v.x;
                eT[(kk + 1) * 128 + w] = v.y;
                eT[(kk + 2) * 128 + w] = v.z;
                eT[(kk + 3) * 128 + w] = v.w;
            }
            __syncthreads();
        }
    }

    // ---- relu + write h1 transposed into eT (aliased) ----
    __syncthreads();   // all reads of e chunk done before overwrite
    float* h1T = eT;
    #pragma unroll
    for (int jj = 0; jj < 8; jj++) {
        int j  = j0 + jj;
        int jp = jj >> 1;
        float2 t0 = upk2(acc[0][jp]);
        float2 t1 = upk2(acc[1][jp]);
        float2 t2 = upk2(acc[2][jp]);
        float2 t3 = upk2(acc[3][jp]);
        float4 vv;
        if (jj & 1) vv = make_float4(t0.y, t1.y, t2.y, t3.y);
        else        vv = make_float4(t0.x, t1.x, t2.x, t3.x);
        vv.x = fmaxf(vv.x, 0.f); vv.y = fmaxf(vv.y, 0.f);
        vv.z = fmaxf(vv.z, 0.f); vv.w = fmaxf(vv.w, 0.f);
        *(float4*)&h1T[j * 128 + ((ecol + ((j >> 2) << 2)) & 127)] = vv;
    }
    __syncthreads();

    // ---- layer 2 GEMM: k = 0..63 over h1 ----
    {
        float4 c0 = *(const float4*)&sB2[j0];
        float4 c1 = *(const float4*)&sB2[j0 + 4];
        #pragma unroll
        for (int q = 0; q < 4; q++) {
            acc[q][0] = pk2(c0.x, c0.y);
            acc[q][1] = pk2(c0.z, c0.w);
            acc[q][2] = pk2(c1.x, c1.y);
            acc[q][3] = pk2(c1.z, c1.w);
        }
    }
    #pragma unroll 4
    for (int k = 0; k < 64; k++) {
        float4 av = *(const float4*)&h1T[k * 128 + ((ecol + ((k >> 2) << 2)) & 127)];
        ulonglong2 blo = *(const ulonglong2*)&sW2[k * 64 + j0];
        ulonglong2 bhi = *(const ulonglong2*)&sW2[k * 64 + j0 + 4];
        u64 s0 = splat2(av.x), s1 = splat2(av.y), s2 = splat2(av.z), s3 = splat2(av.w);
        fma2(acc[0][0], s0, blo.x); fma2(acc[0][1], s0, blo.y);
        fma2(acc[0][2], s0, bhi.x); fma2(acc[0][3], s0, bhi.y);
        fma2(acc[1][0], s1, blo.x); fma2(acc[1][1], s1, blo.y);
        fma2(acc[1][2], s1, bhi.x); fma2(acc[1][3], s1, bhi.y);
        fma2(acc[2][0], s2, blo.x); fma2(acc[2][1], s2, blo.y);
        fma2(acc[2][2], s2, bhi.x); fma2(acc[2][3], s2, bhi.y);
        fma2(acc[3][0], s3, blo.x); fma2(acc[3][1], s3, blo.y);
        fma2(acc[3][2], s3, bhi.x); fma2(acc[3][3], s3, bhi.y);
    }

    // ---- layer 3: partial dot over this thread's 8 j, reduce over joct lanes ----
    float w3v[8];
    {
        float4 wlo = *(const float4*)&sW3[j0];
        float4 whi = *(const float4*)&sW3[j0 + 4];
        w3v[0]=wlo.x; w3v[1]=wlo.y; w3v[2]=wlo.z; w3v[3]=wlo.w;
        w3v[4]=whi.x; w3v[5]=whi.y; w3v[6]=whi.z; w3v[7]=whi.w;
    }
    float p[4];
    #pragma unroll
    for (int q = 0; q < 4; q++) {
        float s = 0.f;
        #pragma unroll
        for (int jp = 0; jp < 4; jp++) {
            float2 t = upk2(acc[q][jp]);
            s = fmaf(fmaxf(t.x, 0.f), w3v[2*jp],     s);
            s = fmaf(fmaxf(t.y, 0.f), w3v[2*jp + 1], s);
        }
        p[q] = s;
    }
    #pragma unroll
    for (int m = 4; m; m >>= 1) {
        #pragma unroll
        for (int q = 0; q < 4; q++)
            p[q] += __shfl_xor_sync(0xffffffffu, p[q], m);
    }

    if (joct == 0) {
        float bb3 = __ldg(b3);
        if (ebase + 3 < N_EDGES) {
            *(float4*)&out[ebase] = make_float4(p[0]+bb3, p[1]+bb3, p[2]+bb3, p[3]+bb3);
        } else {
            #pragma unroll
            for (int q = 0; q < 4; q++)
                if (ebase + q < N_EDGES) out[ebase + q] = p[q] + bb3;
        }
    }
}

// ============================================================================
extern "C" void kernel_launch(void* const* d_in, const int* in_sizes, int n_in,
                              void* d_out, int out_size)
{
    const int*   ei = (const int*)  d_in[0];
    const float* x  = (const float*)d_in[1];
    const float* e  = (const float*)d_in[2];
    const float* W1 = (const float*)d_in[3];
    const float* b1 = (const float*)d_in[4];
    const float* W2 = (const float*)d_in[5];
    const float* b2 = (const float*)d_in[6];
    const float* W3 = (const float*)d_in[7];
    const float* b3 = (const float*)d_in[8];
    float* out = (float*)d_out;

    (void)in_sizes; (void)n_in; (void)out_size;

    cudaFuncSetAttribute(prep_kernel,
                         cudaFuncAttributeMaxDynamicSharedMemorySize, 98304);
    cudaFuncSetAttribute(edge_kernel,
                         cudaFuncAttributeMaxDynamicSharedMemorySize, 84992);

    prep_kernel<<<782, 256, 98304>>>(x, W1);
    edge_kernel<<<(N_EDGES + TE - 1) / TE, TH, 82688>>>(ei, e, W1, b1, W2, b2, W3, b3, out);
}

// round 5
// speedup vs baseline: 2.9973x; 2.9876x over previous
#include <cuda_runtime.h>
#include <cuda_bf16.h>
#include <cstdint>
#include <cstddef>

#define N_NODES 50000
#define N_EDGES 1000000
#define DIM     128
#define HID     64
#define NT      15625      // 64-edge tiles, exact
#define GRID_E  296

typedef unsigned long long u64;

// Single dynamic-smem symbol shared by both kernels.
extern __shared__ __align__(1024) unsigned char dynsmem[];

// Per-node projection scratch (25.6 MB)
__device__ __align__(16) float g_PA[50048 * HID];
__device__ __align__(16) float g_PB[50048 * HID];

// ---------------- fp32x2 helpers (prep kernel) ----------------
__device__ __forceinline__ float2 upk2(u64 v) {
    float2 r; asm("mov.b64 {%0, %1}, %2;" : "=f"(r.x), "=f"(r.y) : "l"(v)); return r;
}
__device__ __forceinline__ void fma2(u64& d, u64 a, u64 b) {
    asm("fma.rn.f32x2 %0, %1, %2, %3;" : "=l"(d) : "l"(a), "l"(b), "l"(d));
}

// ---------------- warp MMA helpers (sm_100 baseline, no 'a' features) -------
__device__ __forceinline__ uint32_t smem_u32(const void* p) {
    uint32_t a;
    asm("{ .reg .u64 t; cvta.to.shared.u64 t, %1; cvt.u32.u64 %0, t; }" : "=r"(a) : "l"(p));
    return a;
}
__device__ __forceinline__ void ldsm4(uint32_t* r, uint32_t a) {
    asm volatile("ldmatrix.sync.aligned.m8n8.x4.shared.b16 {%0,%1,%2,%3}, [%4];"
        : "=r"(r[0]), "=r"(r[1]), "=r"(r[2]), "=r"(r[3]) : "r"(a));
}
__device__ __forceinline__ void ldsm4t(uint32_t* r, uint32_t a) {
    asm volatile("ldmatrix.sync.aligned.m8n8.x4.trans.shared.b16 {%0,%1,%2,%3}, [%4];"
        : "=r"(r[0]), "=r"(r[1]), "=r"(r[2]), "=r"(r[3]) : "r"(a));
}
__device__ __forceinline__ void mma16816(float* c, const uint32_t* a,
                                         uint32_t b0, uint32_t b1) {
    asm volatile(
        "mma.sync.aligned.m16n8k16.row.col.f32.bf16.bf16.f32 "
        "{%0,%1,%2,%3}, {%4,%5,%6,%7}, {%8,%9}, {%0,%1,%2,%3};"
        : "+f"(c[0]), "+f"(c[1]), "+f"(c[2]), "+f"(c[3])
        : "r"(a[0]), "r"(a[1]), "r"(a[2]), "r"(a[3]), "r"(b0), "r"(b1));
}

// split helpers: hi = truncate-to-bf16 (top 16 bits), lo = exact residual -> rn bf16
__device__ __forceinline__ uint32_t pack_hi2(float x, float y) {
    return __byte_perm(__float_as_uint(x), __float_as_uint(y), 0x7632);
}
__device__ __forceinline__ float hi_of(float x) {
    return __uint_as_float(__float_as_uint(x) & 0xFFFF0000u);
}
__device__ __forceinline__ uint32_t pack_lo2(float x, float y) {
    float lx = x - hi_of(x), ly = y - hi_of(y);
    uint32_t r;
    asm("cvt.rn.bf16x2.f32 %0, %1, %2;" : "=r"(r) : "f"(ly), "f"(lx));
    return r;
}

// smem byte offsets
#define OFF_W1HI 0        // [k:128][j:64] bf16, 16KB, chunk swizzle c^=(k&7)
#define OFF_W1LO 16384
#define OFF_W2HI 32768    // [k:64][j:64] bf16, 8KB
#define OFF_W2LO 40960
#define OFF_AHI  49152    // e tile hi [m:64][k:128] (16KB); aliased: h1 hi [m:64][k:64]
#define OFF_ALO  65536    // e tile lo; aliased: h1 lo
#define OFF_PAB  81920    // [m:64][j:64] f32 (16KB), group swizzle g^=(m&7)
#define OFF_B1   98304
#define OFF_B2   98560
#define OFF_W3   98816
#define SMEM_EDGE 99072

// ============================================================================
// Prep (unchanged, known-good): PA/PB node projections.
// ============================================================================
__global__ void __launch_bounds__(256, 2) prep_kernel(
    const float* __restrict__ x, const float* __restrict__ W1)
{
    float* smem = (float*)dynsmem;
    float* sW  = smem;
    float* sxT = smem + 16384;

    const int tid   = threadIdx.x;
    const int nbase = blockIdx.x * 64;

    for (int idx = tid; idx < 16384; idx += 256) {
        int j = idx >> 8, c = idx & 255;
        sW[idx] = W1[j * 384 + c];
    }
    for (int idx = tid; idx < 8192; idx += 256) {
        int nl = idx >> 7, k = idx & 127;
        int node = nbase + nl;
        float v = (node < N_NODES) ? x[node * DIM + k] : 0.f;
        sxT[(k >> 2) * 256 + (nl << 2) + (k & 3)] = v;
    }
    __syncthreads();

    const int lane  = tid & 31;
    const int w     = tid >> 5;
    const int jbase = w * 8;

    u64 aA[2][8], aB[2][8];
    #pragma unroll
    for (int n = 0; n < 2; n++)
        #pragma unroll
        for (int jj = 0; jj < 8; jj++) { aA[n][jj] = 0ull; aB[n][jj] = 0ull; }

    const ulonglong2* xT2 = (const ulonglong2*)sxT;

    #pragma unroll 1
    for (int k4 = 0; k4 < 32; k4++) {
        ulonglong2 xv0 = xT2[(k4 << 6) + lane];
        ulonglong2 xv1 = xT2[(k4 << 6) + 32 + lane];
        #pragma unroll
        for (int jj = 0; jj < 8; jj++) {
            const ulonglong2* wr = (const ulonglong2*)(sW + ((jbase + jj) << 8));
            ulonglong2 wa = wr[k4];
            ulonglong2 wb = wr[32 + k4];
            fma2(aA[0][jj], xv0.x, wa.x);  fma2(aA[0][jj], xv0.y, wa.y);
            fma2(aA[1][jj], xv1.x, wa.x);  fma2(aA[1][jj], xv1.y, wa.y);
            fma2(aB[0][jj], xv0.x, wb.x);  fma2(aB[0][jj], xv0.y, wb.y);
            fma2(aB[1][jj], xv1.x, wb.x);  fma2(aB[1][jj], xv1.y, wb.y);
        }
    }

    #pragma unroll
    for (int n = 0; n < 2; n++) {
        int node = nbase + n * 32 + lane;
        if (node < N_NODES) {
            #pragma unroll
            for (int jj = 0; jj < 8; jj++) {
                float2 a = upk2(aA[n][jj]);
                float2 b = upk2(aB[n][jj]);
                g_PA[node * HID + jbase + jj] = a.x + a.y;
                g_PB[node * HID + jbase + jj] = b.x + b.y;
            }
        }
    }
}

// ============================================================================
// Edge kernel — persistent split-bf16 warp-MMA (mma.sync m16n8k16).
// 128 threads = 4 warps; warp w owns edges [w*16, w*16+16) x all 64 j.
// ============================================================================
__global__ void __launch_bounds__(128, 2) edge_kernel(
    const int*   __restrict__ ei,
    const float* __restrict__ e,
    const float* __restrict__ W1,
    const float* __restrict__ b1,
    const float* __restrict__ W2,
    const float* __restrict__ b2,
    const float* __restrict__ W3,
    const float* __restrict__ b3,
    float*       __restrict__ out)
{
    unsigned char* smem = dynsmem;
    const uint32_t sbase = smem_u32(smem);
    const int tid  = threadIdx.x;
    const int lane = tid & 31;
    const int m0   = (tid >> 5) * 16;     // warp's edge-row base within tile

    // ---- stage weights hi/lo (once per block) ----
    for (int i = tid; i < 8192; i += 128) {          // W1c: j = i>>7, k = i&127
        int j = i >> 7, k = i & 127;
        float v = W1[j * 384 + 256 + k];
        uint32_t off = (uint32_t)(k * 128 + ((((j >> 3) ^ (k & 7)) << 4)) + (j & 7) * 2);
        *(unsigned short*)(smem + OFF_W1HI + off) =
            (unsigned short)(__float_as_uint(v) >> 16);
        float lo = v - hi_of(v);
        *(__nv_bfloat16*)(smem + OFF_W1LO + off) = __float2bfloat16_rn(lo);
    }
    for (int i = tid; i < 4096; i += 128) {          // W2: j = i>>6, k = i&63
        int j = i >> 6, k = i & 63;
        float v = W2[j * 64 + k];
        uint32_t off = (uint32_t)(k * 128 + ((((j >> 3) ^ (k & 7)) << 4)) + (j & 7) * 2);
        *(unsigned short*)(smem + OFF_W2HI + off) =
            (unsigned short)(__float_as_uint(v) >> 16);
        float lo = v - hi_of(v);
        *(__nv_bfloat16*)(smem + OFF_W2LO + off) = __float2bfloat16_rn(lo);
    }
    if (tid < 64) {
        ((float*)(smem + OFF_B1))[tid] = b1[tid];
        ((float*)(smem + OFF_B2))[tid] = b2[tid];
        ((float*)(smem + OFF_W3))[tid] = W3[tid];
    }
    const float b3v = __ldg(b3);
    __syncthreads();

    const float* sB2p = (const float*)(smem + OFF_B2);
    const float* sW3p = (const float*)(smem + OFF_W3);

    for (int t = blockIdx.x; t < NT; t += GRID_E) {
        const int ebase = t * 64;

        // ================= stage e tile (split hi/lo, swizzled) =============
        #pragma unroll
        for (int it = 0; it < 16; it++) {
            int idx = it * 128 + tid;               // 2048 float4 chunks
            int m = idx >> 5, f4 = idx & 31;
            float4 v = __ldg((const float4*)(e + (size_t)(ebase + m) * DIM) + f4);
            uint32_t h0 = pack_hi2(v.x, v.y), h1 = pack_hi2(v.z, v.w);
            uint32_t l0 = pack_lo2(v.x, v.y), l1 = pack_lo2(v.z, v.w);
            int c = f4 >> 1, h = f4 & 1;
            uint32_t off = (uint32_t)(m * 256 + (((c ^ (m & 7)) << 4)) + h * 8);
            *(uint2*)(smem + OFF_AHI + off) = make_uint2(h0, h1);
            *(uint2*)(smem + OFF_ALO + off) = make_uint2(l0, l1);
        }
        // ================= stage PAB = PA[src] + PB[dst] + b1 ===============
        {
            int m = tid >> 1, jh = (tid & 1) * 32;
            int ge = ebase + m;
            int s = __ldg(ei + ge);
            int d = __ldg(ei + N_EDGES + ge);
            const float4* pa = (const float4*)(g_PA + (size_t)s * HID + jh);
            const float4* pb = (const float4*)(g_PB + (size_t)d * HID + jh);
            const float4* bb = (const float4*)((const float*)(smem + OFF_B1) + jh);
            #pragma unroll
            for (int q = 0; q < 8; q++) {
                float4 a = pa[q], b = pb[q], c = bb[q];
                float4 r = make_float4(a.x + b.x + c.x, a.y + b.y + c.y,
                                       a.z + b.z + c.z, a.w + b.w + c.w);
                int j0 = jh + q * 4;
                uint32_t off = (uint32_t)((m * 64 +
                    (((j0 >> 3) ^ (m & 7)) << 3) + (j0 & 7)) * 4);
                *(float4*)(smem + OFF_PAB + off) = r;
            }
        }
        __syncthreads();

        // ================= layer 1 MMA: 3 terms, K=128 ======================
        float acc[8][4];
        #pragma unroll
        for (int nt = 0; nt < 8; nt++)
            #pragma unroll
            for (int q = 0; q < 4; q++) acc[nt][q] = 0.f;

        {
            const int rowa = m0 + (lane & 15);
            #pragma unroll
            for (int kc = 0; kc < 8; kc++) {
                uint32_t ah[4], al[4];
                int ca = kc * 2 + (lane >> 4);
                uint32_t aoff = (uint32_t)(rowa * 256 + (((ca ^ (rowa & 7)) << 4)));
                ldsm4(ah, sbase + OFF_AHI + aoff);
                ldsm4(al, sbase + OFF_ALO + aoff);
                int krow = kc * 16 + (lane & 15);
                #pragma unroll
                for (int np = 0; np < 4; np++) {
                    int g = 2 * np + (lane >> 4);
                    uint32_t boff = (uint32_t)(krow * 128 + (((g ^ (krow & 7)) << 4)));
                    uint32_t bh[4], bl[4];
                    ldsm4t(bh, sbase + OFF_W1HI + boff);
                    mma16816(acc[2*np],     ah, bh[0], bh[1]);
                    mma16816(acc[2*np + 1], ah, bh[2], bh[3]);
                    mma16816(acc[2*np],     al, bh[0], bh[1]);
                    mma16816(acc[2*np + 1], al, bh[2], bh[3]);
                    ldsm4t(bl, sbase + OFF_W1LO + boff);
                    mma16816(acc[2*np],     ah, bl[0], bl[1]);
                    mma16816(acc[2*np + 1], ah, bl[2], bl[3]);
                }
            }
        }
        __syncthreads();   // all warps done reading e tile before h1 overwrites it

        // ================= epilogue 1: +PAB, relu, split -> sH ==============
        {
            const int r0 = m0 + (lane >> 2);
            const int r1 = r0 + 8;
            #pragma unroll
            for (int nt = 0; nt < 8; nt++) {
                int j0 = nt * 8 + (lane & 3) * 2;
                float2 p0 = *(const float2*)(smem + OFF_PAB +
                    (uint32_t)((r0 * 64 + (((nt ^ (r0 & 7)) << 3)) + (j0 & 7)) * 4));
                float2 p1 = *(const float2*)(smem + OFF_PAB +
                    (uint32_t)((r1 * 64 + (((nt ^ (r1 & 7)) << 3)) + (j0 & 7)) * 4));
                float v0 = fmaxf(acc[nt][0] + p0.x, 0.f);
                float v1 = fmaxf(acc[nt][1] + p0.y, 0.f);
                float v2 = fmaxf(acc[nt][2] + p1.x, 0.f);
                float v3 = fmaxf(acc[nt][3] + p1.y, 0.f);
                uint32_t o0 = (uint32_t)(r0 * 128 + (((nt ^ (r0 & 7)) << 4)) + (j0 & 7) * 2);
                uint32_t o1 = (uint32_t)(r1 * 128 + (((nt ^ (r1 & 7)) << 4)) + (j0 & 7) * 2);
                *(uint32_t*)(smem + OFF_AHI + o0) = pack_hi2(v0, v1);
                *(uint32_t*)(smem + OFF_ALO + o0) = pack_lo2(v0, v1);
                *(uint32_t*)(smem + OFF_AHI + o1) = pack_hi2(v2, v3);
                *(uint32_t*)(smem + OFF_ALO + o1) = pack_lo2(v2, v3);
            }
        }
        __syncthreads();

        // ================= layer 2 MMA: 3 terms, K=64 =======================
        #pragma unroll
        for (int nt = 0; nt < 8; nt++)
            #pragma unroll
            for (int q = 0; q < 4; q++) acc[nt][q] = 0.f;
        {
            const int rowa = m0 + (lane & 15);
            #pragma unroll
            for (int kc = 0; kc < 4; kc++) {
                uint32_t ah[4], al[4];
                int ca = kc * 2 + (lane >> 4);
                uint32_t aoff = (uint32_t)(rowa * 128 + (((ca ^ (rowa & 7)) << 4)));
                ldsm4(ah, sbase + OFF_AHI + aoff);
                ldsm4(al, sbase + OFF_ALO + aoff);
                int krow = kc * 16 + (lane & 15);
                #pragma unroll
                for (int np = 0; np < 4; np++) {
                    int g = 2 * np + (lane >> 4);
                    uint32_t boff = (uint32_t)(krow * 128 + (((g ^ (krow & 7)) << 4)));
                    uint32_t bh[4], bl[4];
                    ldsm4t(bh, sbase + OFF_W2HI + boff);
                    mma16816(acc[2*np],     ah, bh[0], bh[1]);
                    mma16816(acc[2*np + 1], ah, bh[2], bh[3]);
                    mma16816(acc[2*np],     al, bh[0], bh[1]);
                    mma16816(acc[2*np + 1], al, bh[2], bh[3]);
                    ldsm4t(bl, sbase + OFF_W2LO + boff);
                    mma16816(acc[2*np],     ah, bl[0], bl[1]);
                    mma16816(acc[2*np + 1], ah, bl[2], bl[3]);
                }
            }
        }

        // ================= epilogue 2: +b2, relu, dot W3, reduce ============
        {
            const int r0 = m0 + (lane >> 2);
            float pr0 = 0.f, pr1 = 0.f;
            #pragma unroll
            for (int nt = 0; nt < 8; nt++) {
                int j0 = nt * 8 + (lane & 3) * 2;
                float2 bb = *(const float2*)(sB2p + j0);
                float2 ww = *(const float2*)(sW3p + j0);
                pr0 = fmaf(fmaxf(acc[nt][0] + bb.x, 0.f), ww.x, pr0);
                pr0 = fmaf(fmaxf(acc[nt][1] + bb.y, 0.f), ww.y, pr0);
                pr1 = fmaf(fmaxf(acc[nt][2] + bb.x, 0.f), ww.x, pr1);
                pr1 = fmaf(fmaxf(acc[nt][3] + bb.y, 0.f), ww.y, pr1);
            }
            pr0 += __shfl_xor_sync(0xffffffffu, pr0, 1);
            pr0 += __shfl_xor_sync(0xffffffffu, pr0, 2);
            pr1 += __shfl_xor_sync(0xffffffffu, pr1, 1);
            pr1 += __shfl_xor_sync(0xffffffffu, pr1, 2);
            if ((lane & 3) == 0) {
                out[ebase + r0]     = pr0 + b3v;
                out[ebase + r0 + 8] = pr1 + b3v;
            }
        }
        __syncthreads();   // next tile's staging overwrites sA/sPAB
    }
}

// ============================================================================
extern "C" void kernel_launch(void* const* d_in, const int* in_sizes, int n_in,
                              void* d_out, int out_size)
{
    const int*   ei = (const int*)  d_in[0];
    const float* x  = (const float*)d_in[1];
    const float* e  = (const float*)d_in[2];
    const float* W1 = (const float*)d_in[3];
    const float* b1 = (const float*)d_in[4];
    const float* W2 = (const float*)d_in[5];
    const float* b2 = (const float*)d_in[6];
    const float* W3 = (const float*)d_in[7];
    const float* b3 = (const float*)d_in[8];
    float* out = (float*)d_out;

    (void)in_sizes; (void)n_in; (void)out_size;

    cudaFuncSetAttribute(prep_kernel,
                         cudaFuncAttributeMaxDynamicSharedMemorySize, 98304);
    cudaFuncSetAttribute(edge_kernel,
                         cudaFuncAttributeMaxDynamicSharedMemorySize, SMEM_EDGE);

    prep_kernel<<<782, 256, 98304>>>(x, W1);
    edge_kernel<<<GRID_E, 128, SMEM_EDGE>>>(ei, e, W1, b1, W2, b2, W3, b3, out);
}